// round 1
// baseline (speedup 1.0000x reference)
#include <cuda_runtime.h>
#include <cstdint>

// Problem constants
#define N_ROWS  32768          // 32*32*32 flattened latent vectors
#define DIM     512            // embedding_dim
#define KCODES  512            // num_embeddings (== DIM, required by the dim=0 norm)
#define Q_ELEMS (N_ROWS * DIM) // 16,777,216
// Output layout (flattened tuple, f32):
//   [0, Q_ELEMS)                      quantized_st
//   [Q_ELEMS]                         vq_loss
//   [Q_ELEMS+1, Q_ELEMS+1+N*K)        one_hot
//   [Q_ELEMS+1+N*K, +N_ROWS)          indices (as float)
#define LOSS_OFF Q_ELEMS
#define OH_OFF   (Q_ELEMS + 1)
#define IDX_OFF  (OH_OFF + N_ROWS * KCODES)

#define NB_QL 2048             // blocks for quantize+loss kernel (fixed => deterministic)

// Scratch (no allocations allowed)
__device__ float  g_rownorm[N_ROWS];
__device__ float  g_colnorm[KCODES];
__device__ int    g_idx[N_ROWS];
__device__ double g_partial[NB_QL];

// ---------------------------------------------------------------------------
// colnorm[k] = sum_j E[j][k]^2   (dim=0 norm, faithful to the reference)
// ---------------------------------------------------------------------------
__global__ void k_colnorm(const float* __restrict__ emb) {
    int k = blockIdx.x * blockDim.x + threadIdx.x;
    if (k >= KCODES) return;
    float s = 0.f;
    for (int j = 0; j < KCODES; j++) {
        float v = emb[(size_t)j * DIM + k];
        s += v * v;
    }
    g_colnorm[k] = s;
}

// ---------------------------------------------------------------------------
// rownorm[n] = sum_d x[n][d]^2   (one warp per row)
// ---------------------------------------------------------------------------
__global__ void k_rownorm(const float* __restrict__ lat) {
    int warp = (blockIdx.x * blockDim.x + threadIdx.x) >> 5;
    int lane = threadIdx.x & 31;
    if (warp >= N_ROWS) return;
    const float* x = lat + (size_t)warp * DIM;
    float s = 0.f;
    for (int t = lane; t < DIM; t += 32) {
        float v = x[t];
        s += v * v;
    }
    #pragma unroll
    for (int o = 16; o > 0; o >>= 1) s += __shfl_xor_sync(0xffffffffu, s, o);
    if (lane == 0) g_rownorm[warp] = s;
}

// ---------------------------------------------------------------------------
// Main kernel: dots = X @ E^T with running argmin of
//   dist = fl( fl(rownorm + colnorm[k]) - 2*dot )
// Tie-break = first (lowest) k, matching jnp.argmin, via u64 (dist_bits<<32)|k.
// Uses packed fma.rn.f32x2 (double-rate fp32 on Blackwell).
// Tiling: 64 rows x 128 codes per block, K staged in shared in 32-wide chunks.
// ---------------------------------------------------------------------------
#define MB 64
#define KB 128
#define DK 32
#define XSTRIDE 68    // 64 + 4 pad (keeps 16B alignment, breaks bank conflicts)
#define ESTRIDE 132   // 128 + 4 pad

__global__ __launch_bounds__(256) void k_argmin(const float* __restrict__ lat,
                                                const float* __restrict__ emb) {
    __shared__ __align__(16) float Xs[DK * XSTRIDE];
    __shared__ __align__(16) float Es[DK * ESTRIDE];
    __shared__ float s_cn[KCODES];
    __shared__ float s_rn[MB];
    __shared__ unsigned long long s_best[MB * 16];

    const int tid  = threadIdx.x;
    const int tx   = tid & 15;       // 16 code-groups of 8
    const int ty   = tid >> 4;       // 16 row-groups of 4
    const int row0 = blockIdx.x * MB;

    for (int i = tid; i < KCODES; i += 256) s_cn[i] = g_colnorm[i];
    for (int i = tid; i < MB;     i += 256) s_rn[i] = g_rownorm[row0 + i];

    unsigned long long best[4] = {~0ull, ~0ull, ~0ull, ~0ull};

    for (int kc = 0; kc < KCODES / KB; kc++) {
        const int k0 = kc * KB;

        // Packed accumulators: acc2[r][c] holds dots for codes (tx*8+2c, tx*8+2c+1)
        unsigned long long acc2[4][4];
        #pragma unroll
        for (int r = 0; r < 4; r++)
            #pragma unroll
            for (int c = 0; c < 4; c++) acc2[r][c] = 0ull;

        for (int dc = 0; dc < DIM / DK; dc++) {
            const int d0 = dc * DK;
            __syncthreads();
            // Stage X tile transposed: Xs[d][r]
            for (int i = tid; i < MB * DK; i += 256) {
                int d = i & (DK - 1);
                int r = i >> 5;
                Xs[d * XSTRIDE + r] = lat[(size_t)(row0 + r) * DIM + d0 + d];
            }
            // Stage E tile transposed: Es[d][k]
            for (int i = tid; i < KB * DK; i += 256) {
                int d = i & (DK - 1);
                int k = i >> 5;
                Es[d * ESTRIDE + k] = emb[(size_t)(k0 + k) * DIM + d0 + d];
            }
            __syncthreads();

            #pragma unroll
            for (int d = 0; d < DK; d++) {
                float4 xv = *reinterpret_cast<const float4*>(&Xs[d * XSTRIDE + ty * 4]);
                ulonglong2 ea = *reinterpret_cast<const ulonglong2*>(&Es[d * ESTRIDE + tx * 8]);
                ulonglong2 eb = *reinterpret_cast<const ulonglong2*>(&Es[d * ESTRIDE + tx * 8 + 4]);
                unsigned long long e2[4] = {ea.x, ea.y, eb.x, eb.y};

                unsigned int xb[4] = {__float_as_uint(xv.x), __float_as_uint(xv.y),
                                      __float_as_uint(xv.z), __float_as_uint(xv.w)};
                unsigned long long x2[4];
                #pragma unroll
                for (int r = 0; r < 4; r++)
                    asm("mov.b64 %0, {%1, %1};" : "=l"(x2[r]) : "r"(xb[r]));

                #pragma unroll
                for (int r = 0; r < 4; r++)
                    #pragma unroll
                    for (int c = 0; c < 4; c++)
                        asm("fma.rn.f32x2 %0, %1, %2, %0;"
                            : "+l"(acc2[r][c]) : "l"(x2[r]), "l"(e2[c]));
            }
        }

        // Epilogue for this 128-code chunk: distances + running best
        #pragma unroll
        for (int r = 0; r < 4; r++) {
            float rn = s_rn[ty * 4 + r];
            #pragma unroll
            for (int c = 0; c < 4; c++) {
                unsigned int lo, hi;
                asm("mov.b64 {%0, %1}, %2;" : "=r"(lo), "=r"(hi) : "l"(acc2[r][c]));
                float dA = __uint_as_float(lo);
                float dB = __uint_as_float(hi);
                int   kA = k0 + tx * 8 + c * 2;
                float a0 = rn + s_cn[kA];         // fp32 round, matches (rn+cn)
                float a1 = rn + s_cn[kA + 1];
                float dist0 = a0 - 2.0f * dA;     // single round (2*dot exact)
                float dist1 = a1 - 2.0f * dB;
                unsigned long long c0 =
                    ((unsigned long long)__float_as_uint(dist0) << 32) | (unsigned)kA;
                unsigned long long c1 =
                    ((unsigned long long)__float_as_uint(dist1) << 32) | (unsigned)(kA + 1);
                if (c0 < best[r]) best[r] = c0;
                if (c1 < best[r]) best[r] = c1;
            }
        }
    }

    #pragma unroll
    for (int r = 0; r < 4; r++) s_best[(ty * 4 + r) * 16 + tx] = best[r];
    __syncthreads();
    if (tid < MB) {
        unsigned long long m = s_best[tid * 16];
        #pragma unroll
        for (int t = 1; t < 16; t++) {
            unsigned long long v = s_best[tid * 16 + t];
            if (v < m) m = v;
        }
        g_idx[row0 + tid] = (int)(m & 0xffffffffu);
    }
}

// ---------------------------------------------------------------------------
// quantized_st (== quantized numerically) + per-block deterministic loss partials
// ---------------------------------------------------------------------------
__global__ __launch_bounds__(256) void k_quant_loss(const float* __restrict__ lat,
                                                    const float* __restrict__ emb,
                                                    float* __restrict__ out) {
    __shared__ double sh[256];
    double s = 0.0;
    const int stride = NB_QL * 256;
    for (int i = blockIdx.x * 256 + threadIdx.x; i < Q_ELEMS; i += stride) {
        int n = i >> 9;
        int d = i & 511;
        float q = emb[(size_t)g_idx[n] * DIM + d];
        out[i] = q;
        float diff = q - lat[i];
        s += (double)diff * (double)diff;
    }
    sh[threadIdx.x] = s;
    __syncthreads();
    for (int o = 128; o > 0; o >>= 1) {
        if (threadIdx.x < o) sh[threadIdx.x] += sh[threadIdx.x + o];
        __syncthreads();
    }
    if (threadIdx.x == 0) g_partial[blockIdx.x] = sh[0];
}

// ---------------------------------------------------------------------------
// one_hot: out[n][k] = (k == idx[n])
// ---------------------------------------------------------------------------
__global__ void k_onehot(float* __restrict__ out) {
    const int stride = gridDim.x * blockDim.x;
    for (int i = blockIdx.x * blockDim.x + threadIdx.x; i < Q_ELEMS; i += stride) {
        int n = i >> 9;
        int k = i & 511;
        out[OH_OFF + i] = (k == g_idx[n]) ? 1.0f : 0.0f;
    }
}

// ---------------------------------------------------------------------------
// indices as float
// ---------------------------------------------------------------------------
__global__ void k_indices(float* __restrict__ out) {
    int n = blockIdx.x * blockDim.x + threadIdx.x;
    if (n < N_ROWS) out[IDX_OFF + n] = (float)g_idx[n];
}

// ---------------------------------------------------------------------------
// finalize loss: fixed-order reduction of partials, vq_loss = 1.25 * mse
// ---------------------------------------------------------------------------
__global__ void k_finalize(float* __restrict__ out) {
    __shared__ double sh[256];
    double s = 0.0;
    for (int i = threadIdx.x; i < NB_QL; i += 256) s += g_partial[i];
    sh[threadIdx.x] = s;
    __syncthreads();
    for (int o = 128; o > 0; o >>= 1) {
        if (threadIdx.x < o) sh[threadIdx.x] += sh[threadIdx.x + o];
        __syncthreads();
    }
    if (threadIdx.x == 0) {
        double mse = sh[0] / (double)Q_ELEMS;
        out[LOSS_OFF] = (float)(mse * 0.25 + mse);
    }
}

// ---------------------------------------------------------------------------
extern "C" void kernel_launch(void* const* d_in, const int* in_sizes, int n_in,
                              void* d_out, int out_size) {
    const float* lat = (const float*)d_in[0];
    const float* emb = (const float*)d_in[1];
    // Defensive: metadata order should be (latents, embedding_weight)
    if (n_in >= 2 && in_sizes[0] == KCODES * DIM && in_sizes[1] == Q_ELEMS) {
        const float* t = lat; lat = emb; emb = t;
    }
    float* out = (float*)d_out;

    k_colnorm<<<(KCODES + 127) / 128, 128>>>(emb);
    k_rownorm<<<N_ROWS / 8, 256>>>(lat);            // 8 warps/block, 1 row/warp
    k_argmin<<<N_ROWS / MB, 256>>>(lat, emb);
    k_quant_loss<<<NB_QL, 256>>>(lat, emb, out);
    k_onehot<<<2048, 256>>>(out);
    k_indices<<<N_ROWS / 256, 256>>>(out);
    k_finalize<<<1, 256>>>(out);
}

// round 7
// speedup vs baseline: 3.4646x; 3.4646x over previous
#include <cuda_runtime.h>
#include <cuda_fp16.h>
#include <cstdint>

// ---------------------------------------------------------------------------
// Problem constants
// ---------------------------------------------------------------------------
#define N_ROWS  32768
#define DIM     512
#define KCODES  512
#define Q_ELEMS (N_ROWS * DIM)
#define LOSS_OFF Q_ELEMS
#define OH_OFF   (Q_ELEMS + 1)
#define IDX_OFF  (OH_OFF + N_ROWS * KCODES)

#define NB_QL 2048

// GEMM tiling (mma.sync.m16n8k16 f16, compute_100-safe)
#define MT   128                 // rows per CTA
#define NTC  128                 // codes per CTA
#define BK   64                  // K per chunk
#define NCH  24                  // 3 segments * 8 chunks
#define RBLK (N_ROWS / MT)       // 256
#define CBLK (KCODES / NTC)      // 4

// Shared memory layout (f16 tiles padded to 72 columns)
#define TSTRIDE 72
#define ATILE_B (MT * TSTRIDE * 2)       // 18432
#define SA_OFF  0
#define SB_OFF  (2 * ATILE_B)            // 36864
#define CN_OFF  (4 * ATILE_B)            // 73728
#define RED_OFF (CN_OFF + 512)           // 74240
#define SMEM_DYN (RED_OFF + 2 * 128 * 8) // 76288

// ---------------------------------------------------------------------------
// Device scratch (no allocations allowed)
// ---------------------------------------------------------------------------
__device__ __align__(16) __half g_Ah[(size_t)N_ROWS * DIM];
__device__ __align__(16) __half g_Al[(size_t)N_ROWS * DIM];
__device__ __align__(16) __half g_Bh[(size_t)KCODES * DIM];
__device__ __align__(16) __half g_Bl[(size_t)KCODES * DIM];
__device__ float  g_rownorm[N_ROWS];
__device__ float  g_colnorm[KCODES];
__device__ unsigned long long g_part[(size_t)CBLK * N_ROWS];
__device__ int    g_idx[N_ROWS];
__device__ double g_partial[NB_QL];

// ---------------------------------------------------------------------------
// PTX helpers (all compute_100-legal: sm_80-era features)
// ---------------------------------------------------------------------------
__device__ __forceinline__ unsigned smem_u32(const void* p) {
    unsigned a;
    asm("{ .reg .u64 t; cvta.to.shared.u64 t, %1; cvt.u32.u64 %0, t; }" : "=r"(a) : "l"(p));
    return a;
}

__device__ __forceinline__ void cp16(unsigned dst, const void* src) {
    asm volatile("cp.async.cg.shared.global [%0], [%1], 16;" :: "r"(dst), "l"(src));
}
__device__ __forceinline__ void cp_commit() { asm volatile("cp.async.commit_group;"); }
__device__ __forceinline__ void cp_wait1()  { asm volatile("cp.async.wait_group 1;"); }
__device__ __forceinline__ void cp_wait0()  { asm volatile("cp.async.wait_group 0;"); }

__device__ __forceinline__ void ldmx4(unsigned& r0, unsigned& r1, unsigned& r2, unsigned& r3,
                                      unsigned addr) {
    asm volatile("ldmatrix.sync.aligned.m8n8.x4.shared.b16 {%0,%1,%2,%3}, [%4];"
                 : "=r"(r0), "=r"(r1), "=r"(r2), "=r"(r3) : "r"(addr));
}

__device__ __forceinline__ void mma16816(float& c0, float& c1, float& c2, float& c3,
                                         unsigned a0, unsigned a1, unsigned a2, unsigned a3,
                                         unsigned b0, unsigned b1) {
    asm volatile("mma.sync.aligned.m16n8k16.row.col.f32.f16.f16.f32 "
                 "{%0,%1,%2,%3}, {%4,%5,%6,%7}, {%8,%9}, {%0,%1,%2,%3};"
                 : "+f"(c0), "+f"(c1), "+f"(c2), "+f"(c3)
                 : "r"(a0), "r"(a1), "r"(a2), "r"(a3), "r"(b0), "r"(b1));
}

// ---------------------------------------------------------------------------
// Conversion: fp32 -> (fp16 hi, fp16 lo), plain row-major
// ---------------------------------------------------------------------------
__device__ __forceinline__ unsigned pack2(float a, float b) {
    unsigned short ha = __half_as_ushort(__float2half_rn(a));
    unsigned short hb = __half_as_ushort(__float2half_rn(b));
    return (unsigned)ha | ((unsigned)hb << 16);
}

__device__ __forceinline__ void split8(const float* __restrict__ src,
                                       __half* __restrict__ dh,
                                       __half* __restrict__ dl, size_t off) {
    const float4* s4 = (const float4*)(src + off);
    float4 v0 = s4[0], v1 = s4[1];
    float x[8] = {v0.x, v0.y, v0.z, v0.w, v1.x, v1.y, v1.z, v1.w};
    float l[8];
    #pragma unroll
    for (int j = 0; j < 8; j++)
        l[j] = x[j] - __half2float(__float2half_rn(x[j]));
    uint4 hi = make_uint4(pack2(x[0], x[1]), pack2(x[2], x[3]),
                          pack2(x[4], x[5]), pack2(x[6], x[7]));
    uint4 lo = make_uint4(pack2(l[0], l[1]), pack2(l[2], l[3]),
                          pack2(l[4], l[5]), pack2(l[6], l[7]));
    *(uint4*)(dh + off) = hi;
    *(uint4*)(dl + off) = lo;
}

__global__ __launch_bounds__(256) void k_convertA(const float* __restrict__ lat) {
    size_t g = (size_t)blockIdx.x * 256 + threadIdx.x;   // Q_ELEMS/8 threads
    split8(lat, g_Ah, g_Al, g * 8);
}

__global__ __launch_bounds__(256) void k_convertB(const float* __restrict__ emb) {
    size_t g = (size_t)blockIdx.x * 256 + threadIdx.x;   // K*D/8 threads
    split8(emb, g_Bh, g_Bl, g * 8);
}

// ---------------------------------------------------------------------------
// Norms (identical numerics to the passing round-1 kernels)
// ---------------------------------------------------------------------------
__global__ void k_colnorm(const float* __restrict__ emb) {
    int k = blockIdx.x * blockDim.x + threadIdx.x;
    if (k >= KCODES) return;
    float s = 0.f;
    for (int j = 0; j < KCODES; j++) {
        float v = emb[(size_t)j * DIM + k];
        s += v * v;
    }
    g_colnorm[k] = s;
}

__global__ void k_rownorm(const float* __restrict__ lat) {
    int warp = (blockIdx.x * blockDim.x + threadIdx.x) >> 5;
    int lane = threadIdx.x & 31;
    if (warp >= N_ROWS) return;
    const float* x = lat + (size_t)warp * DIM;
    float s = 0.f;
    for (int t = lane; t < DIM; t += 32) {
        float v = x[t];
        s += v * v;
    }
    #pragma unroll
    for (int o = 16; o > 0; o >>= 1) s += __shfl_xor_sync(0xffffffffu, s, o);
    if (lane == 0) g_rownorm[warp] = s;
}

// ---------------------------------------------------------------------------
// GEMM (fp16 3-product fp32 emulation) + fused argmin epilogue.
// grid = RBLK*CBLK, 256 threads (8 warps as 4 row x 2 col).
// ---------------------------------------------------------------------------
__global__ __launch_bounds__(256) void k_gemm_argmin() {
    extern __shared__ char smem[];
    const unsigned S = smem_u32(smem);

    const int tid  = threadIdx.x;
    const int wid  = tid >> 5;
    const int lane = tid & 31;
    const int wm   = wid >> 1;        // 0..3 (row warps)
    const int wn   = wid & 1;         // 0..1 (col warps)
    const int quad = lane >> 2;       // 0..7
    const int qt   = lane & 3;        // 0..3
    const int cb   = blockIdx.x & 3;
    const int rb   = blockIdx.x >> 2;
    const int row0 = rb * MT;
    const int col0 = cb * NTC;

    float* s_cn = (float*)(smem + CN_OFF);
    unsigned long long* s_red = (unsigned long long*)(smem + RED_OFF);

    if (tid < NTC) s_cn[tid] = g_colnorm[col0 + tid];

    // K-loop source tables: segments (Ah,Bh), (Al,Bh), (Ah,Bl)
    const __half* Aseg[3] = {g_Ah + (size_t)row0 * DIM,
                             g_Al + (size_t)row0 * DIM,
                             g_Ah + (size_t)row0 * DIM};
    const __half* Bseg[3] = {g_Bh + (size_t)col0 * DIM,
                             g_Bh + (size_t)col0 * DIM,
                             g_Bl + (size_t)col0 * DIM};

    float acc[2][8][4];
    #pragma unroll
    for (int mt = 0; mt < 2; mt++)
        #pragma unroll
        for (int nt = 0; nt < 8; nt++)
            #pragma unroll
            for (int j = 0; j < 4; j++) acc[mt][nt][j] = 0.f;

    // issue loads for chunk i into buffer buf
    auto load_chunk = [&](int i, int buf) {
        const int seg = i >> 3;
        const int kc  = (i & 7) * BK;
        const __half* As = Aseg[seg];
        const __half* Bs = Bseg[seg];
        #pragma unroll
        for (int j = 0; j < 4; j++) {
            int id = tid + j * 256;          // 0..1023
            int r = id >> 3, c = (id & 7) * 8;
            cp16(S + SA_OFF + buf * ATILE_B + (r * TSTRIDE + c) * 2,
                 As + (size_t)r * DIM + kc + c);
            cp16(S + SB_OFF + buf * ATILE_B + (r * TSTRIDE + c) * 2,
                 Bs + (size_t)r * DIM + kc + c);
        }
        cp_commit();
    };

    load_chunk(0, 0);

    for (int i = 0; i < NCH; i++) {
        const int buf = i & 1;
        if (i + 1 < NCH) { load_chunk(i + 1, buf ^ 1); cp_wait1(); }
        else            { cp_wait0(); }
        __syncthreads();

        const unsigned baseA = S + SA_OFF + buf * ATILE_B;
        const unsigned baseB = S + SB_OFF + buf * ATILE_B;
        const int g  = lane >> 3;
        const int l8 = lane & 7;

        #pragma unroll
        for (int ks = 0; ks < 4; ks++) {
            const int k0 = ks * 16;
            unsigned a[2][4];
            #pragma unroll
            for (int mt = 0; mt < 2; mt++) {
                int r = wm * 32 + mt * 16 + ((g & 1) << 3) + l8;
                int c = k0 + ((g >> 1) << 3);
                ldmx4(a[mt][0], a[mt][1], a[mt][2], a[mt][3],
                      baseA + (r * TSTRIDE + c) * 2);
            }
            unsigned b[4][4];
            #pragma unroll
            for (int np = 0; np < 4; np++) {
                int r = wn * 64 + np * 16 + ((g >> 1) << 3) + l8;
                int c = k0 + ((g & 1) << 3);
                ldmx4(b[np][0], b[np][1], b[np][2], b[np][3],
                      baseB + (r * TSTRIDE + c) * 2);
            }
            #pragma unroll
            for (int mt = 0; mt < 2; mt++)
                #pragma unroll
                for (int np = 0; np < 4; np++) {
                    mma16816(acc[mt][np*2][0],   acc[mt][np*2][1],
                             acc[mt][np*2][2],   acc[mt][np*2][3],
                             a[mt][0], a[mt][1], a[mt][2], a[mt][3],
                             b[np][0], b[np][1]);
                    mma16816(acc[mt][np*2+1][0], acc[mt][np*2+1][1],
                             acc[mt][np*2+1][2], acc[mt][np*2+1][3],
                             a[mt][0], a[mt][1], a[mt][2], a[mt][3],
                             b[np][2], b[np][3]);
                }
        }
        __syncthreads();
    }

    // Epilogue: dist = (rn + cn[k]) - 2*dot ; u64 lexicographic argmin
    float rn[4];
    #pragma unroll
    for (int j = 0; j < 4; j++)
        rn[j] = g_rownorm[row0 + wm * 32 + quad + j * 8];

    unsigned long long best[4] = {~0ull, ~0ull, ~0ull, ~0ull};
    #pragma unroll
    for (int nt = 0; nt < 8; nt++) {
        const int cl = wn * 64 + nt * 8 + qt * 2;
        const float cn0 = s_cn[cl], cn1 = s_cn[cl + 1];
        const unsigned kg = (unsigned)(col0 + cl);
        #pragma unroll
        for (int mt = 0; mt < 2; mt++) {
            float d00 = (rn[mt*2]   + cn0) - 2.0f * acc[mt][nt][0];
            float d01 = (rn[mt*2]   + cn1) - 2.0f * acc[mt][nt][1];
            float d10 = (rn[mt*2+1] + cn0) - 2.0f * acc[mt][nt][2];
            float d11 = (rn[mt*2+1] + cn1) - 2.0f * acc[mt][nt][3];
            unsigned long long c00 = ((unsigned long long)__float_as_uint(d00) << 32) | kg;
            unsigned long long c01 = ((unsigned long long)__float_as_uint(d01) << 32) | (kg+1);
            unsigned long long c10 = ((unsigned long long)__float_as_uint(d10) << 32) | kg;
            unsigned long long c11 = ((unsigned long long)__float_as_uint(d11) << 32) | (kg+1);
            if (c00 < best[mt*2])   best[mt*2]   = c00;
            if (c01 < best[mt*2])   best[mt*2]   = c01;
            if (c10 < best[mt*2+1]) best[mt*2+1] = c10;
            if (c11 < best[mt*2+1]) best[mt*2+1] = c11;
        }
    }
    // reduce over the 4 lanes of each quad (same rows, disjoint cols)
    #pragma unroll
    for (int j = 0; j < 4; j++) {
        #pragma unroll
        for (int o = 1; o <= 2; o <<= 1) {
            unsigned long long v = __shfl_xor_sync(0xffffffffu, best[j], o);
            if (v < best[j]) best[j] = v;
        }
    }
    if (qt == 0) {
        #pragma unroll
        for (int j = 0; j < 4; j++)
            s_red[wn * 128 + wm * 32 + quad + j * 8] = best[j];
    }
    __syncthreads();
    if (tid < 128) {
        unsigned long long a0 = s_red[tid], a1 = s_red[128 + tid];
        g_part[(size_t)cb * N_ROWS + row0 + tid] = (a0 < a1) ? a0 : a1;
    }
}

// ---------------------------------------------------------------------------
// merge the 4 code-block partials -> final index
// ---------------------------------------------------------------------------
__global__ void k_merge() {
    int n = blockIdx.x * blockDim.x + threadIdx.x;
    if (n >= N_ROWS) return;
    unsigned long long m = g_part[n];
    #pragma unroll
    for (int c = 1; c < CBLK; c++) {
        unsigned long long v = g_part[(size_t)c * N_ROWS + n];
        if (v < m) m = v;
    }
    g_idx[n] = (int)(m & 0xffffffffu);
}

// ---------------------------------------------------------------------------
// quantized_st + deterministic loss partials (float4; region starts at offset 0,
// so vector alignment is safe here)
// ---------------------------------------------------------------------------
__global__ __launch_bounds__(256) void k_quant_loss(const float* __restrict__ lat,
                                                    const float* __restrict__ emb,
                                                    float* __restrict__ out) {
    __shared__ double sh[256];
    double s = 0.0;
    const int stride = NB_QL * 256;
    const float4* lat4 = (const float4*)lat;
    const float4* emb4 = (const float4*)emb;
    float4* out4 = (float4*)out;
    for (int i = blockIdx.x * 256 + threadIdx.x; i < Q_ELEMS / 4; i += stride) {
        int n  = i >> 7;
        int d4 = i & 127;
        float4 q = emb4[(size_t)g_idx[n] * 128 + d4];
        float4 x = lat4[i];
        out4[i] = q;
        float dx = q.x - x.x, dy = q.y - x.y, dz = q.z - x.z, dw = q.w - x.w;
        s += (double)(dx * dx + dy * dy + dz * dz + dw * dw);
    }
    sh[threadIdx.x] = s;
    __syncthreads();
    for (int o = 128; o > 0; o >>= 1) {
        if (threadIdx.x < o) sh[threadIdx.x] += sh[threadIdx.x + o];
        __syncthreads();
    }
    if (threadIdx.x == 0) g_partial[blockIdx.x] = sh[0];
}

// ---------------------------------------------------------------------------
// one_hot: SCALAR stores only. The region starts at out + Q_ELEMS + 1 (odd
// float offset => 4-byte aligned only); any float2/float4 access here faults.
// ---------------------------------------------------------------------------
__global__ __launch_bounds__(256) void k_onehot(float* __restrict__ out) {
    const int stride = gridDim.x * blockDim.x;
    for (int i = blockIdx.x * blockDim.x + threadIdx.x; i < N_ROWS * KCODES; i += stride) {
        int n = i >> 9;
        int k = i & 511;
        out[OH_OFF + i] = (k == g_idx[n]) ? 1.0f : 0.0f;
    }
}

// ---------------------------------------------------------------------------
// indices as float
// ---------------------------------------------------------------------------
__global__ void k_indices(float* __restrict__ out) {
    int n = blockIdx.x * blockDim.x + threadIdx.x;
    if (n < N_ROWS) out[IDX_OFF + n] = (float)g_idx[n];
}

// ---------------------------------------------------------------------------
// finalize loss
// ---------------------------------------------------------------------------
__global__ void k_finalize(float* __restrict__ out) {
    __shared__ double sh[256];
    double s = 0.0;
    for (int i = threadIdx.x; i < NB_QL; i += 256) s += g_partial[i];
    sh[threadIdx.x] = s;
    __syncthreads();
    for (int o = 128; o > 0; o >>= 1) {
        if (threadIdx.x < o) sh[threadIdx.x] += sh[threadIdx.x + o];
        __syncthreads();
    }
    if (threadIdx.x == 0) {
        double mse = sh[0] / (double)Q_ELEMS;
        out[LOSS_OFF] = (float)(mse * 0.25 + mse);
    }
}

// ---------------------------------------------------------------------------
extern "C" void kernel_launch(void* const* d_in, const int* in_sizes, int n_in,
                              void* d_out, int out_size) {
    const float* lat = (const float*)d_in[0];
    const float* emb = (const float*)d_in[1];
    if (n_in >= 2 && in_sizes[0] == KCODES * DIM && in_sizes[1] == Q_ELEMS) {
        const float* t = lat; lat = emb; emb = t;
    }
    float* out = (float*)d_out;

    cudaFuncSetAttribute(k_gemm_argmin,
                         cudaFuncAttributeMaxDynamicSharedMemorySize, SMEM_DYN);

    k_convertA<<<Q_ELEMS / 8 / 256, 256>>>(lat);
    k_convertB<<<KCODES * DIM / 8 / 256, 256>>>(emb);
    k_colnorm<<<(KCODES + 127) / 128, 128>>>(emb);
    k_rownorm<<<N_ROWS / 8, 256>>>(lat);
    k_gemm_argmin<<<RBLK * CBLK, 256, SMEM_DYN>>>();
    k_merge<<<N_ROWS / 256, 256>>>();
    k_quant_loss<<<NB_QL, 256>>>(lat, emb, out);
    k_onehot<<<2048, 256>>>(out);
    k_indices<<<N_ROWS / 256, 256>>>(out);
    k_finalize<<<1, 256>>>(out);
}

// round 8
// speedup vs baseline: 4.0267x; 1.1622x over previous
#include <cuda_runtime.h>
#include <cuda_fp16.h>
#include <cstdint>

// ---------------------------------------------------------------------------
// Problem constants
// ---------------------------------------------------------------------------
#define N_ROWS  32768
#define DIM     512
#define KCODES  512
#define Q_ELEMS (N_ROWS * DIM)
#define LOSS_OFF Q_ELEMS
#define OH_OFF   (Q_ELEMS + 1)
#define IDX_OFF  (OH_OFF + N_ROWS * KCODES)

#define NB_QL 2048

// GEMM tiling: M=128 x N=256 per CTA, K chunked by 64, all 3 fp16-split
// products (Ah*Bh, Ah*Bl, Al*Bh) fused per chunk so A streams once.
#define MT   128
#define NTC  256
#define BK   64
#define NKCH (DIM / BK)          // 8
#define RBLK (N_ROWS / MT)       // 256
#define CBLK (KCODES / NTC)      // 2

// Shared memory (tiles padded to 72 cols, same conflict-free layout as r7)
#define TSTRIDE 72
#define AT_B   (MT * TSTRIDE * 2)        // 18432
#define BT_B   (NTC * TSTRIDE * 2)       // 36864
#define AH_OFF 0
#define AL_OFF AT_B
#define BH_OFF (2 * AT_B)
#define BL_OFF (2 * AT_B + BT_B)
#define STAGE_B (2 * AT_B + 2 * BT_B)    // 110592
#define CN_OFF  (2 * STAGE_B)            // 221184
#define RED_OFF (CN_OFF + 1024)          // 222208
#define SMEM_DYN (RED_OFF + 2 * 128 * 8) // 224256  (< 232448 cap)

// ---------------------------------------------------------------------------
// Device scratch
// ---------------------------------------------------------------------------
__device__ __align__(16) __half g_Ah[(size_t)N_ROWS * DIM];
__device__ __align__(16) __half g_Al[(size_t)N_ROWS * DIM];
__device__ __align__(16) __half g_Bh[(size_t)KCODES * DIM];
__device__ __align__(16) __half g_Bl[(size_t)KCODES * DIM];
__device__ float  g_rownorm[N_ROWS];
__device__ float  g_colnorm[KCODES];
__device__ unsigned long long g_part[(size_t)CBLK * N_ROWS];
__device__ int    g_idx[N_ROWS];
__device__ double g_partial[NB_QL];

// ---------------------------------------------------------------------------
// PTX helpers (compute_100-legal)
// ---------------------------------------------------------------------------
__device__ __forceinline__ unsigned smem_u32(const void* p) {
    unsigned a;
    asm("{ .reg .u64 t; cvta.to.shared.u64 t, %1; cvt.u32.u64 %0, t; }" : "=r"(a) : "l"(p));
    return a;
}
__device__ __forceinline__ void cp16(unsigned dst, const void* src) {
    asm volatile("cp.async.cg.shared.global [%0], [%1], 16;" :: "r"(dst), "l"(src));
}
__device__ __forceinline__ void cp_commit() { asm volatile("cp.async.commit_group;"); }
__device__ __forceinline__ void cp_wait1()  { asm volatile("cp.async.wait_group 1;"); }
__device__ __forceinline__ void cp_wait0()  { asm volatile("cp.async.wait_group 0;"); }

__device__ __forceinline__ void ldmx4(unsigned& r0, unsigned& r1, unsigned& r2, unsigned& r3,
                                      unsigned addr) {
    asm volatile("ldmatrix.sync.aligned.m8n8.x4.shared.b16 {%0,%1,%2,%3}, [%4];"
                 : "=r"(r0), "=r"(r1), "=r"(r2), "=r"(r3) : "r"(addr));
}
__device__ __forceinline__ void mma16816(float& c0, float& c1, float& c2, float& c3,
                                         unsigned a0, unsigned a1, unsigned a2, unsigned a3,
                                         unsigned b0, unsigned b1) {
    asm volatile("mma.sync.aligned.m16n8k16.row.col.f32.f16.f16.f32 "
                 "{%0,%1,%2,%3}, {%4,%5,%6,%7}, {%8,%9}, {%0,%1,%2,%3};"
                 : "+f"(c0), "+f"(c1), "+f"(c2), "+f"(c3)
                 : "r"(a0), "r"(a1), "r"(a2), "r"(a3), "r"(b0), "r"(b1));
}

// ---------------------------------------------------------------------------
// fp32 -> (fp16 hi, fp16 lo)
// ---------------------------------------------------------------------------
__device__ __forceinline__ unsigned pack2(float a, float b) {
    unsigned short ha = __half_as_ushort(__float2half_rn(a));
    unsigned short hb = __half_as_ushort(__float2half_rn(b));
    return (unsigned)ha | ((unsigned)hb << 16);
}

// convertA fused with rownorm: block = 256 threads = 4 rows.
// Phase 1 converts (float4 loads) and stages the fp32 row into smem.
// Phase 2 computes rownorm from smem with the EXACT round-1 loop (same order).
__global__ __launch_bounds__(256) void k_convA_rn(const float* __restrict__ lat) {
    __shared__ float sx[4][DIM];
    const int tid = threadIdx.x;
    const int nl  = tid >> 6;          // 0..3 local row
    const int c   = (tid & 63) * 8;    // col of 8-elem chunk
    const size_t n = (size_t)blockIdx.x * 4 + nl;
    const size_t off = n * DIM + c;

    const float4* s4 = (const float4*)(lat + off);
    float4 v0 = s4[0], v1 = s4[1];
    float x[8] = {v0.x, v0.y, v0.z, v0.w, v1.x, v1.y, v1.z, v1.w};
    float l[8];
    #pragma unroll
    for (int j = 0; j < 8; j++) {
        sx[nl][c + j] = x[j];
        l[j] = x[j] - __half2float(__float2half_rn(x[j]));
    }
    uint4 hi = make_uint4(pack2(x[0], x[1]), pack2(x[2], x[3]),
                          pack2(x[4], x[5]), pack2(x[6], x[7]));
    uint4 lo = make_uint4(pack2(l[0], l[1]), pack2(l[2], l[3]),
                          pack2(l[4], l[5]), pack2(l[6], l[7]));
    *(uint4*)(g_Ah + off) = hi;
    *(uint4*)(g_Al + off) = lo;

    __syncthreads();
    const int wid  = tid >> 5;
    const int lane = tid & 31;
    if (wid < 4) {
        float s = 0.f;
        for (int t = lane; t < DIM; t += 32) {
            float v = sx[wid][t];
            s += v * v;
        }
        #pragma unroll
        for (int o = 16; o > 0; o >>= 1) s += __shfl_xor_sync(0xffffffffu, s, o);
        if (lane == 0) g_rownorm[(size_t)blockIdx.x * 4 + wid] = s;
    }
}

__global__ __launch_bounds__(256) void k_convertB(const float* __restrict__ emb) {
    size_t g = (size_t)blockIdx.x * 256 + threadIdx.x;   // K*D/8 threads
    size_t off = g * 8;
    const float4* s4 = (const float4*)(emb + off);
    float4 v0 = s4[0], v1 = s4[1];
    float x[8] = {v0.x, v0.y, v0.z, v0.w, v1.x, v1.y, v1.z, v1.w};
    float l[8];
    #pragma unroll
    for (int j = 0; j < 8; j++)
        l[j] = x[j] - __half2float(__float2half_rn(x[j]));
    uint4 hi = make_uint4(pack2(x[0], x[1]), pack2(x[2], x[3]),
                          pack2(x[4], x[5]), pack2(x[6], x[7]));
    uint4 lo = make_uint4(pack2(l[0], l[1]), pack2(l[2], l[3]),
                          pack2(l[4], l[5]), pack2(l[6], l[7]));
    *(uint4*)(g_Bh + off) = hi;
    *(uint4*)(g_Bl + off) = lo;
}

// colnorm: unchanged numerics
__global__ void k_colnorm(const float* __restrict__ emb) {
    int k = blockIdx.x * blockDim.x + threadIdx.x;
    if (k >= KCODES) return;
    float s = 0.f;
    for (int j = 0; j < KCODES; j++) {
        float v = emb[(size_t)j * DIM + k];
        s += v * v;
    }
    g_colnorm[k] = s;
}

// ---------------------------------------------------------------------------
// GEMM: 3 fused fp16-split products per K-chunk + argmin epilogue.
// grid = RBLK*CBLK = 512; 256 threads; warps: wm=wid>>1 (4 row), wn=wid&1 (2 col).
// Per warp: M=32 (mt 0..1), N=128 (nt 0..15).
// ---------------------------------------------------------------------------
__global__ __launch_bounds__(256) void k_gemm_argmin() {
    extern __shared__ char smem[];
    const unsigned S = smem_u32(smem);

    const int tid  = threadIdx.x;
    const int wid  = tid >> 5;
    const int lane = tid & 31;
    const int wm   = wid >> 1;
    const int wn   = wid & 1;
    const int quad = lane >> 2;
    const int qt   = lane & 3;
    const int cb   = blockIdx.x & 1;
    const int rb   = blockIdx.x >> 1;
    const int row0 = rb * MT;
    const int col0 = cb * NTC;

    float* s_cn = (float*)(smem + CN_OFF);
    unsigned long long* s_red = (unsigned long long*)(smem + RED_OFF);

    s_cn[tid] = g_colnorm[col0 + tid];   // 256 threads, 256 cols

    const __half* Ah = g_Ah + (size_t)row0 * DIM;
    const __half* Al = g_Al + (size_t)row0 * DIM;
    const __half* Bh = g_Bh + (size_t)col0 * DIM;
    const __half* Bl = g_Bl + (size_t)col0 * DIM;

    float acc[2][16][4];
    #pragma unroll
    for (int mt = 0; mt < 2; mt++)
        #pragma unroll
        for (int nt = 0; nt < 16; nt++)
            #pragma unroll
            for (int j = 0; j < 4; j++) acc[mt][nt][j] = 0.f;

    auto load_chunk = [&](int i, int buf) {
        const int kc = i * BK;
        const unsigned st = S + buf * STAGE_B;
        // A tiles: 128x64 -> 1024 cp16 each
        #pragma unroll
        for (int j = 0; j < 4; j++) {
            int id = tid + j * 256;
            int r = id >> 3, c = (id & 7) * 8;
            unsigned d = (unsigned)((r * TSTRIDE + c) * 2);
            cp16(st + AH_OFF + d, Ah + (size_t)r * DIM + kc + c);
            cp16(st + AL_OFF + d, Al + (size_t)r * DIM + kc + c);
        }
        // B tiles: 256x64 -> 2048 cp16 each
        #pragma unroll
        for (int j = 0; j < 8; j++) {
            int id = tid + j * 256;
            int r = id >> 3, c = (id & 7) * 8;
            unsigned d = (unsigned)((r * TSTRIDE + c) * 2);
            cp16(st + BH_OFF + d, Bh + (size_t)r * DIM + kc + c);
            cp16(st + BL_OFF + d, Bl + (size_t)r * DIM + kc + c);
        }
        cp_commit();
    };

    load_chunk(0, 0);

    const int g  = lane >> 3;
    const int l8 = lane & 7;

    for (int i = 0; i < NKCH; i++) {
        const int buf = i & 1;
        if (i + 1 < NKCH) { load_chunk(i + 1, buf ^ 1); cp_wait1(); }
        else             { cp_wait0(); }
        __syncthreads();

        const unsigned st = S + buf * STAGE_B;

        #pragma unroll
        for (int ks = 0; ks < 4; ks++) {
            const int k0 = ks * 16;
            unsigned ah[2][4], al[2][4];
            #pragma unroll
            for (int mt = 0; mt < 2; mt++) {
                int r = wm * 32 + mt * 16 + ((g & 1) << 3) + l8;
                int c = k0 + ((g >> 1) << 3);
                unsigned d = (unsigned)((r * TSTRIDE + c) * 2);
                ldmx4(ah[mt][0], ah[mt][1], ah[mt][2], ah[mt][3], st + AH_OFF + d);
                ldmx4(al[mt][0], al[mt][1], al[mt][2], al[mt][3], st + AL_OFF + d);
            }
            #pragma unroll
            for (int np = 0; np < 8; np++) {
                int r = wn * 128 + np * 16 + ((g >> 1) << 3) + l8;
                int c = k0 + ((g & 1) << 3);
                unsigned d = (unsigned)((r * TSTRIDE + c) * 2);
                unsigned bh[4], bl[4];
                ldmx4(bh[0], bh[1], bh[2], bh[3], st + BH_OFF + d);
                ldmx4(bl[0], bl[1], bl[2], bl[3], st + BL_OFF + d);
                #pragma unroll
                for (int mt = 0; mt < 2; mt++) {
                    mma16816(acc[mt][np*2][0],   acc[mt][np*2][1],
                             acc[mt][np*2][2],   acc[mt][np*2][3],
                             ah[mt][0], ah[mt][1], ah[mt][2], ah[mt][3], bh[0], bh[1]);
                    mma16816(acc[mt][np*2+1][0], acc[mt][np*2+1][1],
                             acc[mt][np*2+1][2], acc[mt][np*2+1][3],
                             ah[mt][0], ah[mt][1], ah[mt][2], ah[mt][3], bh[2], bh[3]);
                    mma16816(acc[mt][np*2][0],   acc[mt][np*2][1],
                             acc[mt][np*2][2],   acc[mt][np*2][3],
                             al[mt][0], al[mt][1], al[mt][2], al[mt][3], bh[0], bh[1]);
                    mma16816(acc[mt][np*2+1][0], acc[mt][np*2+1][1],
                             acc[mt][np*2+1][2], acc[mt][np*2+1][3],
                             al[mt][0], al[mt][1], al[mt][2], al[mt][3], bh[2], bh[3]);
                    mma16816(acc[mt][np*2][0],   acc[mt][np*2][1],
                             acc[mt][np*2][2],   acc[mt][np*2][3],
                             ah[mt][0], ah[mt][1], ah[mt][2], ah[mt][3], bl[0], bl[1]);
                    mma16816(acc[mt][np*2+1][0], acc[mt][np*2+1][1],
                             acc[mt][np*2+1][2], acc[mt][np*2+1][3],
                             ah[mt][0], ah[mt][1], ah[mt][2], ah[mt][3], bl[2], bl[3]);
                }
            }
        }
        __syncthreads();
    }

    // Epilogue: dist = (rn + cn[k]) - 2*dot ; u64 lexicographic argmin
    float rn[4];
    #pragma unroll
    for (int j = 0; j < 4; j++)
        rn[j] = g_rownorm[row0 + wm * 32 + quad + j * 8];   // rows quad + {0,8,16,24}

    unsigned long long best[4] = {~0ull, ~0ull, ~0ull, ~0ull};
    #pragma unroll
    for (int nt = 0; nt < 16; nt++) {
        const int cl = wn * 128 + nt * 8 + qt * 2;
        const float cn0 = s_cn[cl], cn1 = s_cn[cl + 1];
        const unsigned kg = (unsigned)(col0 + cl);
        #pragma unroll
        for (int mt = 0; mt < 2; mt++) {
            // acc rows: c0,c1 -> quad (j = mt*2), c2,c3 -> quad+8 (j = mt*2+1)
            float d00 = (rn[mt*2]   + cn0) - 2.0f * acc[mt][nt][0];
            float d01 = (rn[mt*2]   + cn1) - 2.0f * acc[mt][nt][1];
            float d10 = (rn[mt*2+1] + cn0) - 2.0f * acc[mt][nt][2];
            float d11 = (rn[mt*2+1] + cn1) - 2.0f * acc[mt][nt][3];
            unsigned long long c00 = ((unsigned long long)__float_as_uint(d00) << 32) | kg;
            unsigned long long c01 = ((unsigned long long)__float_as_uint(d01) << 32) | (kg+1);
            unsigned long long c10 = ((unsigned long long)__float_as_uint(d10) << 32) | kg;
            unsigned long long c11 = ((unsigned long long)__float_as_uint(d11) << 32) | (kg+1);
            if (c00 < best[mt*2])   best[mt*2]   = c00;
            if (c01 < best[mt*2])   best[mt*2]   = c01;
            if (c10 < best[mt*2+1]) best[mt*2+1] = c10;
            if (c11 < best[mt*2+1]) best[mt*2+1] = c11;
        }
    }
    #pragma unroll
    for (int j = 0; j < 4; j++) {
        #pragma unroll
        for (int o = 1; o <= 2; o <<= 1) {
            unsigned long long v = __shfl_xor_sync(0xffffffffu, best[j], o);
            if (v < best[j]) best[j] = v;
        }
    }
    if (qt == 0) {
        #pragma unroll
        for (int j = 0; j < 4; j++)
            s_red[wn * 128 + wm * 32 + quad + j * 8] = best[j];
    }
    __syncthreads();
    if (tid < 128) {
        unsigned long long a0 = s_red[tid], a1 = s_red[128 + tid];
        g_part[(size_t)cb * N_ROWS + row0 + tid] = (a0 < a1) ? a0 : a1;
    }
}

// merge the 2 code-block partials -> index (int + float output)
__global__ void k_merge(float* __restrict__ out) {
    int n = blockIdx.x * blockDim.x + threadIdx.x;
    if (n >= N_ROWS) return;
    unsigned long long a = g_part[n];
    unsigned long long b = g_part[(size_t)N_ROWS + n];
    int idx = (int)((a < b ? a : b) & 0xffffffffu);
    g_idx[n] = idx;
    out[IDX_OFF + n] = (float)idx;
}

// ---------------------------------------------------------------------------
// Fused outputs: quantized (float4) + loss partials + one_hot (scalar; region
// is only 4-byte aligned at OH_OFF = Q_ELEMS+1 -> NO vector access there)
// ---------------------------------------------------------------------------
__global__ __launch_bounds__(256) void k_out(const float* __restrict__ lat,
                                             const float* __restrict__ emb,
                                             float* __restrict__ out) {
    __shared__ double sh[256];
    double s = 0.0;
    const int stride = NB_QL * 256;
    const float4* lat4 = (const float4*)lat;
    const float4* emb4 = (const float4*)emb;
    float4* out4 = (float4*)out;
    for (int i = blockIdx.x * 256 + threadIdx.x; i < Q_ELEMS / 4; i += stride) {
        int n  = i >> 7;
        int d4 = i & 127;
        float4 q = emb4[(size_t)g_idx[n] * 128 + d4];
        float4 x = lat4[i];
        out4[i] = q;
        float dx = q.x - x.x, dy = q.y - x.y, dz = q.z - x.z, dw = q.w - x.w;
        s += (double)(dx * dx + dy * dy + dz * dz + dw * dw);
    }
    // one_hot (scalar stores)
    for (int i = blockIdx.x * 256 + threadIdx.x; i < N_ROWS * KCODES; i += stride) {
        int n = i >> 9;
        int k = i & 511;
        out[OH_OFF + i] = (k == g_idx[n]) ? 1.0f : 0.0f;
    }
    sh[threadIdx.x] = s;
    __syncthreads();
    for (int o = 128; o > 0; o >>= 1) {
        if (threadIdx.x < o) sh[threadIdx.x] += sh[threadIdx.x + o];
        __syncthreads();
    }
    if (threadIdx.x == 0) g_partial[blockIdx.x] = sh[0];
}

__global__ void k_finalize(float* __restrict__ out) {
    __shared__ double sh[256];
    double s = 0.0;
    for (int i = threadIdx.x; i < NB_QL; i += 256) s += g_partial[i];
    sh[threadIdx.x] = s;
    __syncthreads();
    for (int o = 128; o > 0; o >>= 1) {
        if (threadIdx.x < o) sh[threadIdx.x] += sh[threadIdx.x + o];
        __syncthreads();
    }
    if (threadIdx.x == 0) {
        double mse = sh[0] / (double)Q_ELEMS;
        out[LOSS_OFF] = (float)(mse * 0.25 + mse);
    }
}

// ---------------------------------------------------------------------------
extern "C" void kernel_launch(void* const* d_in, const int* in_sizes, int n_in,
                              void* d_out, int out_size) {
    const float* lat = (const float*)d_in[0];
    const float* emb = (const float*)d_in[1];
    if (n_in >= 2 && in_sizes[0] == KCODES * DIM && in_sizes[1] == Q_ELEMS) {
        const float* t = lat; lat = emb; emb = t;
    }
    float* out = (float*)d_out;

    cudaFuncSetAttribute(k_gemm_argmin,
                         cudaFuncAttributeMaxDynamicSharedMemorySize, SMEM_DYN);

    k_convA_rn<<<N_ROWS / 4, 256>>>(lat);
    k_convertB<<<KCODES * DIM / 8 / 256, 256>>>(emb);
    k_colnorm<<<(KCODES + 127) / 128, 128>>>(emb);
    k_gemm_argmin<<<RBLK * CBLK, 256, SMEM_DYN>>>();
    k_merge<<<N_ROWS / 256, 256>>>(out);
    k_out<<<NB_QL, 256>>>(lat, emb, out);
    k_finalize<<<1, 256>>>(out);
}